// round 11
// baseline (speedup 1.0000x reference)
#include <cuda_runtime.h>
#include <math.h>

#define NNODE 20000
#define PCOLS 640
#define CAP   96      // max degree per (relation, dst); Poisson(16), P(>96) ~ 1e-44

// ---------------- scratch (device globals; no allocation allowed) ----------------
__device__ float g_WcatA[128 * 640];
__device__ float g_WcatB[128 * 640];
__device__ float g_bcatA[640];
__device__ float g_bcatB[640];
__device__ float g_Pa[(size_t)NNODE * PCOLS];   // [K_aa | K_ab | V_aa | V_ab | Q_a]
__device__ float g_Pb[(size_t)NNODE * PCOLS];   // [K_ba | K_bb | V_ba | V_bb | Q_b]
__device__ int   g_cnt[4][NNODE];
__device__ int   g_srcS[4][(size_t)NNODE * CAP];  // padded dst-buckets of src indices
__device__ float g_agg[2][(size_t)NNODE * 128];   // normalized+mean-combined aggregates

struct GraphArgs { const int* src[4]; const int* dst[4]; int E[4]; };

// ---------------- prep: fold per-head DxD transforms into 128x640 weight ----------
__global__ void prep_kernel(const float* __restrict__ Wk, const float* __restrict__ bk,
                            const float* __restrict__ Wq, const float* __restrict__ bq,
                            const float* __restrict__ Wv, const float* __restrict__ bv,
                            const float* __restrict__ att, const float* __restrict__ msg)
{
    int t = blockIdx.y;
    int idx = blockIdx.x * blockDim.x + threadIdx.x;
    if (idx >= 129 * 640) return;
    int i = idx / 640;
    int c = idx % 640;
    int blk = c >> 7;
    int e16 = c & 127;
    int h = e16 >> 4;
    int ec = e16 & 15;

    float val;
    if (blk == 4) {
        val = (i < 128) ? Wq[t * 16384 + i * 128 + e16] : bq[t * 128 + e16];
    } else {
        const float* Wbase;
        const float* bbase;
        const float* T;
        int rel;
        if (blk < 2) { Wbase = Wk + t * 16384; bbase = bk + t * 128; rel = t * 2 + blk; T = att; }
        else         { Wbase = Wv + t * 16384; bbase = bv + t * 128; rel = t * 2 + (blk - 2); T = msg; }
        const float* Trow = T + ((rel * 8 + h) * 16) * 16 + ec;
        float s = 0.f;
        if (i < 128) {
            const float* wrow = Wbase + i * 128 + h * 16;
#pragma unroll
            for (int d = 0; d < 16; d++) s += wrow[d] * Trow[d * 16];
        } else {
            const float* brow = bbase + h * 16;
#pragma unroll
            for (int d = 0; d < 16; d++) s += brow[d] * Trow[d * 16];
        }
        val = s;
    }

    float* Wc = t ? g_WcatB : g_WcatA;
    float* bc = t ? g_bcatB : g_bcatA;
    if (i < 128) Wc[i * 640 + c] = val;
    else         bc[c] = val;
}

// ---------------- bucket build: zero counters, then direct scatter ----------------
__global__ void zero_cnt_kernel()
{
    int i = blockIdx.x * blockDim.x + threadIdx.x;
    if (i < 4 * NNODE) ((int*)g_cnt)[i] = 0;
}

__global__ void scatter_kernel(GraphArgs ga)
{
    int r = blockIdx.y;
    int i = blockIdx.x * blockDim.x + threadIdx.x;
    if (i >= ga.E[r]) return;
    int d = ga.dst[r][i];
    int pos = atomicAdd(&g_cnt[r][d], 1);
    if (pos < CAP)
        g_srcS[r][(size_t)d * CAP + pos] = ga.src[r][i];
}

// ---------------- fp32 GEMM 128x128x16, 8x8 microtile, double-buffered smem --------
__global__ __launch_bounds__(256) void gemm_bias_kernel(
    const float* __restrict__ A0, const float* __restrict__ W0,
    const float* __restrict__ bias0, float* __restrict__ C0,
    const float* __restrict__ A1, const float* __restrict__ W1,
    const float* __restrict__ bias1, float* __restrict__ C1,
    int M, int Ncols, int K)
{
    const float* A    = blockIdx.z ? A1 : A0;
    const float* W    = blockIdx.z ? W1 : W0;
    const float* bias = blockIdx.z ? bias1 : bias0;
    float*       C    = blockIdx.z ? C1 : C0;

    __shared__ float As[2][16][132];
    __shared__ float Bs[2][16][128];
    const int tid = threadIdx.x;
    const int tx = tid & 15;
    const int ty = tid >> 4;
    const int rowBlock = blockIdx.y * 128;
    const int colBlock = blockIdx.x * 128;

    float acc[8][8];
#pragma unroll
    for (int i = 0; i < 8; i++)
#pragma unroll
        for (int j = 0; j < 8; j++) acc[i][j] = 0.f;

    const int lr = tid >> 1;
    const int lkc = (tid & 1) << 3;
    const int bk = tid >> 4;
    const int bc = (tid & 15) << 3;
    const int grow = rowBlock + lr;

    // prologue: tile 0 -> regs -> smem[0]
    float4 av0 = make_float4(0.f, 0.f, 0.f, 0.f), av1 = av0, bv0, bv1;
    if (grow < M) {
        const float* ap = A + (size_t)grow * K + lkc;
        av0 = *(const float4*)ap;
        av1 = *(const float4*)(ap + 4);
    }
    {
        const float* wp = W + (size_t)bk * Ncols + colBlock + bc;
        bv0 = *(const float4*)wp;
        bv1 = *(const float4*)(wp + 4);
    }
    As[0][lkc + 0][lr] = av0.x; As[0][lkc + 1][lr] = av0.y;
    As[0][lkc + 2][lr] = av0.z; As[0][lkc + 3][lr] = av0.w;
    As[0][lkc + 4][lr] = av1.x; As[0][lkc + 5][lr] = av1.y;
    As[0][lkc + 6][lr] = av1.z; As[0][lkc + 7][lr] = av1.w;
    *(float4*)&Bs[0][bk][bc]     = bv0;
    *(float4*)&Bs[0][bk][bc + 4] = bv1;
    __syncthreads();

    int cur = 0;
    for (int kk = 0; kk < K; kk += 16) {
        const bool more = (kk + 16 < K);
        if (more) {   // prefetch next tile into regs (LDGs in flight during compute)
            if (grow < M) {
                const float* ap = A + (size_t)grow * K + kk + 16 + lkc;
                av0 = *(const float4*)ap;
                av1 = *(const float4*)(ap + 4);
            }
            const float* wp = W + (size_t)(kk + 16 + bk) * Ncols + colBlock + bc;
            bv0 = *(const float4*)wp;
            bv1 = *(const float4*)(wp + 4);
        }

#pragma unroll
        for (int k = 0; k < 16; k++) {
            float4 a0 = *(const float4*)&As[cur][k][ty * 8];
            float4 a1 = *(const float4*)&As[cur][k][ty * 8 + 4];
            float4 b0 = *(const float4*)&Bs[cur][k][tx * 8];
            float4 b1 = *(const float4*)&Bs[cur][k][tx * 8 + 4];
            float a[8] = {a0.x, a0.y, a0.z, a0.w, a1.x, a1.y, a1.z, a1.w};
            float b[8] = {b0.x, b0.y, b0.z, b0.w, b1.x, b1.y, b1.z, b1.w};
#pragma unroll
            for (int i = 0; i < 8; i++)
#pragma unroll
                for (int j = 0; j < 8; j++) acc[i][j] += a[i] * b[j];
        }

        if (more) {   // store prefetched tile into the other buffer
            int nxt = cur ^ 1;
            As[nxt][lkc + 0][lr] = av0.x; As[nxt][lkc + 1][lr] = av0.y;
            As[nxt][lkc + 2][lr] = av0.z; As[nxt][lkc + 3][lr] = av0.w;
            As[nxt][lkc + 4][lr] = av1.x; As[nxt][lkc + 5][lr] = av1.y;
            As[nxt][lkc + 6][lr] = av1.z; As[nxt][lkc + 7][lr] = av1.w;
            *(float4*)&Bs[nxt][bk][bc]     = bv0;
            *(float4*)&Bs[nxt][bk][bc + 4] = bv1;
            __syncthreads();
            cur = nxt;
        }
    }
#pragma unroll
    for (int i = 0; i < 8; i++) {
        int row = rowBlock + ty * 8 + i;
        if (row < M) {
            float* cp = C + (size_t)row * Ncols + colBlock + tx * 8;
            float4 o0, o1;
            o0.x = acc[i][0] + bias[colBlock + tx * 8 + 0];
            o0.y = acc[i][1] + bias[colBlock + tx * 8 + 1];
            o0.z = acc[i][2] + bias[colBlock + tx * 8 + 2];
            o0.w = acc[i][3] + bias[colBlock + tx * 8 + 3];
            o1.x = acc[i][4] + bias[colBlock + tx * 8 + 4];
            o1.y = acc[i][5] + bias[colBlock + tx * 8 + 5];
            o1.z = acc[i][6] + bias[colBlock + tx * 8 + 6];
            o1.w = acc[i][7] + bias[colBlock + tx * 8 + 7];
            *(float4*)cp = o0;
            *(float4*)(cp + 4) = o1;
        }
    }
}

// ---------------- per-relation edge accumulation (register softmax, unroll 4) ------
__device__ __forceinline__ void edge_step(
    const float* __restrict__ Kb, const float* __restrict__ Vb, int s,
    float4 q, float prih, float4& acc, float& ss, int lane)
{
    float4 k = ((const float4*)(Kb + (size_t)s * PCOLS))[lane];
    float4 v = ((const float4*)(Vb + (size_t)s * PCOLS))[lane];
    float p = k.x * q.x + k.y * q.y + k.z * q.z + k.w * q.w;
    p += __shfl_xor_sync(0xffffffffu, p, 1);
    p += __shfl_xor_sync(0xffffffffu, p, 2);
    float e = __expf(p * prih);
    ss += e;
    acc.x += e * v.x; acc.y += e * v.y; acc.z += e * v.z; acc.w += e * v.w;
}

__device__ __forceinline__ void rel_accum(
    const float* __restrict__ Kb, const float* __restrict__ Vb,
    const int* __restrict__ bucket, int n,
    float4 q, float prih, int lane, float4& acc, float& ss)
{
    acc = make_float4(0.f, 0.f, 0.f, 0.f);
    ss = 0.f;
    int i = 0;
    for (; i + 4 <= n; i += 4) {
        int s0 = bucket[i], s1 = bucket[i + 1], s2 = bucket[i + 2], s3 = bucket[i + 3];
        float4 k0 = ((const float4*)(Kb + (size_t)s0 * PCOLS))[lane];
        float4 v0 = ((const float4*)(Vb + (size_t)s0 * PCOLS))[lane];
        float4 k1 = ((const float4*)(Kb + (size_t)s1 * PCOLS))[lane];
        float4 v1 = ((const float4*)(Vb + (size_t)s1 * PCOLS))[lane];
        float4 k2 = ((const float4*)(Kb + (size_t)s2 * PCOLS))[lane];
        float4 v2 = ((const float4*)(Vb + (size_t)s2 * PCOLS))[lane];
        float4 k3 = ((const float4*)(Kb + (size_t)s3 * PCOLS))[lane];
        float4 v3 = ((const float4*)(Vb + (size_t)s3 * PCOLS))[lane];
        float p0 = k0.x * q.x + k0.y * q.y + k0.z * q.z + k0.w * q.w;
        float p1 = k1.x * q.x + k1.y * q.y + k1.z * q.z + k1.w * q.w;
        float p2 = k2.x * q.x + k2.y * q.y + k2.z * q.z + k2.w * q.w;
        float p3 = k3.x * q.x + k3.y * q.y + k3.z * q.z + k3.w * q.w;
        p0 += __shfl_xor_sync(0xffffffffu, p0, 1);
        p1 += __shfl_xor_sync(0xffffffffu, p1, 1);
        p2 += __shfl_xor_sync(0xffffffffu, p2, 1);
        p3 += __shfl_xor_sync(0xffffffffu, p3, 1);
        p0 += __shfl_xor_sync(0xffffffffu, p0, 2);
        p1 += __shfl_xor_sync(0xffffffffu, p1, 2);
        p2 += __shfl_xor_sync(0xffffffffu, p2, 2);
        p3 += __shfl_xor_sync(0xffffffffu, p3, 2);
        float e0 = __expf(p0 * prih);
        float e1 = __expf(p1 * prih);
        float e2 = __expf(p2 * prih);
        float e3 = __expf(p3 * prih);
        ss += (e0 + e1) + (e2 + e3);
        acc.x += e0 * v0.x + e1 * v1.x + e2 * v2.x + e3 * v3.x;
        acc.y += e0 * v0.y + e1 * v1.y + e2 * v2.y + e3 * v3.y;
        acc.z += e0 * v0.z + e1 * v1.z + e2 * v2.z + e3 * v3.z;
        acc.w += e0 * v0.w + e1 * v1.w + e2 * v2.w + e3 * v3.w;
    }
    for (; i < n; i++)
        edge_step(Kb, Vb, bucket[i], q, prih, acc, ss, lane);
}

// ---------------- aggregate: one warp per (dst node, node type); both relations ----
__global__ __launch_bounds__(256) void agg_kernel(const float* __restrict__ pri)
{
    int t = blockIdx.y;                 // node type: 0=a, 1=b
    int wid = threadIdx.x >> 5;
    int lane = threadIdx.x & 31;
    int d = blockIdx.x * 8 + wid;
    if (d >= NNODE) return;
    int hh = lane >> 2;

    const float* Qb = (t ? g_Pb : g_Pa) + 512;
    int r0 = t ? 1 : 0;     // a-type src relation
    int r1 = t ? 3 : 2;     // b-type src relation
    const float* K0 = g_Pa + (t ? 128 : 0);
    const float* V0 = g_Pa + (t ? 384 : 256);
    const float* K1 = g_Pb + (t ? 128 : 0);
    const float* V1 = g_Pb + (t ? 384 : 256);

    float4 q = ((const float4*)(Qb + (size_t)d * PCOLS))[lane];
    float pri0 = __ldg(pri + r0 * 8 + hh) * 0.25f;
    float pri1 = __ldg(pri + r1 * 8 + hh) * 0.25f;

    int n0 = min(g_cnt[r0][d], CAP);
    int n1 = min(g_cnt[r1][d], CAP);

    float4 a0, a1;
    float s0, s1;
    rel_accum(K0, V0, &g_srcS[r0][(size_t)d * CAP], n0, q, pri0, lane, a0, s0);
    rel_accum(K1, V1, &g_srcS[r1][(size_t)d * CAP], n1, q, pri1, lane, a1, s1);

    float i0 = (s0 > 0.f) ? 0.5f / s0 : 0.f;
    float i1 = (s1 > 0.f) ? 0.5f / s1 : 0.f;
    float4 o;
    o.x = a0.x * i0 + a1.x * i1;
    o.y = a0.y * i0 + a1.y * i1;
    o.z = a0.z * i0 + a1.z * i1;
    o.w = a0.w * i0 + a1.w * i1;
    *(float4*)(&g_agg[t][(size_t)d * 128 + lane * 4]) = o;
}

// ---------------- final GEMM + skip epilogue (both node types, blockIdx.z) ----------
__global__ __launch_bounds__(256) void gemm_final_kernel(
    const float* __restrict__ Wa, const float* __restrict__ ba,
    const float* __restrict__ h_a, const float* __restrict__ h_b,
    const float* __restrict__ skipv, float* __restrict__ outbase, int M)
{
    const int K = 128, Ncols = 128;
    const int t = blockIdx.z;
    const float* Agg  = g_agg[t];
    const float* W    = Wa + t * 16384;
    const float* bias = ba + t * 128;
    const float* hres = t ? h_b : h_a;
    float* out = outbase + (size_t)t * M * 128;

    __shared__ float As[2][16][132];
    __shared__ float Bs[2][16][128];
    const int tid = threadIdx.x;
    const int tx = tid & 15;
    const int ty = tid >> 4;
    const int rowBlock = blockIdx.y * 128;

    float acc[8][8];
#pragma unroll
    for (int i = 0; i < 8; i++)
#pragma unroll
        for (int j = 0; j < 8; j++) acc[i][j] = 0.f;

    const int lr = tid >> 1;
    const int lkc = (tid & 1) << 3;
    const int bk = tid >> 4;
    const int bc = (tid & 15) << 3;
    const int grow = rowBlock + lr;

    // prologue
    float4 av0 = make_float4(0.f, 0.f, 0.f, 0.f), av1 = av0, bv0, bv1;
    if (grow < M) {
        const float* ap = Agg + (size_t)grow * K + lkc;
        av0 = *(const float4*)ap;
        av1 = *(const float4*)(ap + 4);
    }
    {
        const float* wp = W + (size_t)bk * Ncols + bc;
        bv0 = *(const float4*)wp;
        bv1 = *(const float4*)(wp + 4);
    }
    As[0][lkc + 0][lr] = av0.x; As[0][lkc + 1][lr] = av0.y;
    As[0][lkc + 2][lr] = av0.z; As[0][lkc + 3][lr] = av0.w;
    As[0][lkc + 4][lr] = av1.x; As[0][lkc + 5][lr] = av1.y;
    As[0][lkc + 6][lr] = av1.z; As[0][lkc + 7][lr] = av1.w;
    *(float4*)&Bs[0][bk][bc]     = bv0;
    *(float4*)&Bs[0][bk][bc + 4] = bv1;
    __syncthreads();

    int cur = 0;
    for (int kk = 0; kk < K; kk += 16) {
        const bool more = (kk + 16 < K);
        if (more) {
            if (grow < M) {
                const float* ap = Agg + (size_t)grow * K + kk + 16 + lkc;
                av0 = *(const float4*)ap;
                av1 = *(const float4*)(ap + 4);
            }
            const float* wp = W + (size_t)(kk + 16 + bk) * Ncols + bc;
            bv0 = *(const float4*)wp;
            bv1 = *(const float4*)(wp + 4);
        }

#pragma unroll
        for (int k = 0; k < 16; k++) {
            float4 a0 = *(const float4*)&As[cur][k][ty * 8];
            float4 a1 = *(const float4*)&As[cur][k][ty * 8 + 4];
            float4 b0 = *(const float4*)&Bs[cur][k][tx * 8];
            float4 b1 = *(const float4*)&Bs[cur][k][tx * 8 + 4];
            float a[8] = {a0.x, a0.y, a0.z, a0.w, a1.x, a1.y, a1.z, a1.w};
            float b[8] = {b0.x, b0.y, b0.z, b0.w, b1.x, b1.y, b1.z, b1.w};
#pragma unroll
            for (int i = 0; i < 8; i++)
#pragma unroll
                for (int j = 0; j < 8; j++) acc[i][j] += a[i] * b[j];
        }

        if (more) {
            int nxt = cur ^ 1;
            As[nxt][lkc + 0][lr] = av0.x; As[nxt][lkc + 1][lr] = av0.y;
            As[nxt][lkc + 2][lr] = av0.z; As[nxt][lkc + 3][lr] = av0.w;
            As[nxt][lkc + 4][lr] = av1.x; As[nxt][lkc + 5][lr] = av1.y;
            As[nxt][lkc + 6][lr] = av1.z; As[nxt][lkc + 7][lr] = av1.w;
            *(float4*)&Bs[nxt][bk][bc]     = bv0;
            *(float4*)&Bs[nxt][bk][bc + 4] = bv1;
            __syncthreads();
            cur = nxt;
        }
    }

    float al = 1.f / (1.f + expf(-skipv[t]));
    float om = 1.f - al;
#pragma unroll
    for (int i = 0; i < 8; i++) {
        int row = rowBlock + ty * 8 + i;
        if (row < M) {
            float* op = out + (size_t)row * Ncols + tx * 8;
            const float* hp = hres + (size_t)row * Ncols + tx * 8;
            float4 h0 = *(const float4*)hp;
            float4 h1 = *(const float4*)(hp + 4);
            float4 o0, o1;
            o0.x = al * (acc[i][0] + bias[tx * 8 + 0]) + om * h0.x;
            o0.y = al * (acc[i][1] + bias[tx * 8 + 1]) + om * h0.y;
            o0.z = al * (acc[i][2] + bias[tx * 8 + 2]) + om * h0.z;
            o0.w = al * (acc[i][3] + bias[tx * 8 + 3]) + om * h0.w;
            o1.x = al * (acc[i][4] + bias[tx * 8 + 4]) + om * h1.x;
            o1.y = al * (acc[i][5] + bias[tx * 8 + 5]) + om * h1.y;
            o1.z = al * (acc[i][6] + bias[tx * 8 + 6]) + om * h1.z;
            o1.w = al * (acc[i][7] + bias[tx * 8 + 7]) + om * h1.w;
            *(float4*)op = o0;
            *(float4*)(op + 4) = o1;
        }
    }
}

// ---------------- launch ----------------
extern "C" void kernel_launch(void* const* d_in, const int* in_sizes, int n_in,
                              void* d_out, int out_size)
{
    const float* h_a  = (const float*)d_in[0];
    const float* h_b  = (const float*)d_in[1];
    const float* Wk   = (const float*)d_in[2];
    const float* bk   = (const float*)d_in[3];
    const float* Wq   = (const float*)d_in[4];
    const float* bq   = (const float*)d_in[5];
    const float* Wv   = (const float*)d_in[6];
    const float* bv   = (const float*)d_in[7];
    const float* Wa   = (const float*)d_in[8];
    const float* ba   = (const float*)d_in[9];
    const float* att  = (const float*)d_in[10];
    const float* msg  = (const float*)d_in[11];
    const float* pri  = (const float*)d_in[12];
    const float* skip = (const float*)d_in[13];

    GraphArgs ga;
    int Emax = 0;
    for (int r = 0; r < 4; r++) {
        ga.src[r] = (const int*)d_in[14 + 2 * r];
        ga.dst[r] = (const int*)d_in[15 + 2 * r];
        ga.E[r] = in_sizes[14 + 2 * r];
        if (ga.E[r] > Emax) Emax = ga.E[r];
    }

    float *Pa, *Pb, *WcA, *WcB, *bcA, *bcB;
    cudaGetSymbolAddress((void**)&Pa,  g_Pa);
    cudaGetSymbolAddress((void**)&Pb,  g_Pb);
    cudaGetSymbolAddress((void**)&WcA, g_WcatA);
    cudaGetSymbolAddress((void**)&WcB, g_WcatB);
    cudaGetSymbolAddress((void**)&bcA, g_bcatA);
    cudaGetSymbolAddress((void**)&bcB, g_bcatB);

    // bucket build: zero counters, then direct padded scatter (no hist/scan)
    zero_cnt_kernel<<<(4 * NNODE + 255) / 256, 256>>>();
    prep_kernel<<<dim3((129 * 640 + 255) / 256, 2), 256>>>(Wk, bk, Wq, bq, Wv, bv, att, msg);
    scatter_kernel<<<dim3((Emax + 255) / 256, 4), 256>>>(ga);

    // projections (both node types, one launch)
    gemm_bias_kernel<<<dim3(PCOLS / 128, (NNODE + 127) / 128, 2), 256>>>(
        h_a, WcA, bcA, Pa, h_b, WcB, bcB, Pb, NNODE, PCOLS, 128);

    // per-node attention aggregation (no atomics, unroll-4 MLP)
    agg_kernel<<<dim3((NNODE + 7) / 8, 2), 256>>>(pri);

    // both final GEMMs in one launch (blockIdx.z)
    gemm_final_kernel<<<dim3(1, (NNODE + 127) / 128, 2), 256>>>(
        Wa, ba, h_a, h_b, skip, (float*)d_out, NNODE);
}

// round 12
// speedup vs baseline: 1.3940x; 1.3940x over previous
#include <cuda_runtime.h>
#include <math.h>

#define NNODE 20000
#define PCOLS 640
#define CAP   96      // max degree per (relation, dst); Poisson(16), P(>96) ~ 1e-44

// ---------------- scratch (device globals; no allocation allowed) ----------------
__device__ float g_WcatA[128 * 640];
__device__ float g_WcatB[128 * 640];
__device__ float g_bcatA[640];
__device__ float g_bcatB[640];
__device__ float g_Pa[(size_t)NNODE * PCOLS];   // [K_aa | K_ab | V_aa | V_ab | Q_a]
__device__ float g_Pb[(size_t)NNODE * PCOLS];   // [K_ba | K_bb | V_ba | V_bb | Q_b]
__device__ int   g_cnt[4][NNODE];
__device__ int   g_srcS[4][(size_t)NNODE * CAP];  // padded dst-buckets of src indices
__device__ float g_agg[2][(size_t)NNODE * 128];   // normalized+mean-combined aggregates

struct GraphArgs { const int* src[4]; const int* dst[4]; int E[4]; };

// ---------------- tf32 helpers ----------------
__device__ __forceinline__ unsigned f2tf(float x)
{
    unsigned u;
    asm("cvt.rna.tf32.f32 %0, %1;" : "=r"(u) : "f"(x));
    return u;
}

__device__ __forceinline__ void mma_tf32(float* c, const unsigned* a, const unsigned* b)
{
    asm volatile(
        "mma.sync.aligned.m16n8k8.row.col.f32.tf32.tf32.f32 "
        "{%0,%1,%2,%3}, {%4,%5,%6,%7}, {%8,%9}, {%0,%1,%2,%3};"
        : "+f"(c[0]), "+f"(c[1]), "+f"(c[2]), "+f"(c[3])
        : "r"(a[0]), "r"(a[1]), "r"(a[2]), "r"(a[3]), "r"(b[0]), "r"(b[1]));
}

// ---------------- prep: fold per-head DxD transforms into 128x640 weight ----------
__global__ void prep_kernel(const float* __restrict__ Wk, const float* __restrict__ bk,
                            const float* __restrict__ Wq, const float* __restrict__ bq,
                            const float* __restrict__ Wv, const float* __restrict__ bv,
                            const float* __restrict__ att, const float* __restrict__ msg)
{
    int t = blockIdx.y;
    int idx = blockIdx.x * blockDim.x + threadIdx.x;
    if (idx >= 129 * 640) return;
    int i = idx / 640;
    int c = idx % 640;
    int blk = c >> 7;
    int e16 = c & 127;
    int h = e16 >> 4;
    int ec = e16 & 15;

    float val;
    if (blk == 4) {
        val = (i < 128) ? Wq[t * 16384 + i * 128 + e16] : bq[t * 128 + e16];
    } else {
        const float* Wbase;
        const float* bbase;
        const float* T;
        int rel;
        if (blk < 2) { Wbase = Wk + t * 16384; bbase = bk + t * 128; rel = t * 2 + blk; T = att; }
        else         { Wbase = Wv + t * 16384; bbase = bv + t * 128; rel = t * 2 + (blk - 2); T = msg; }
        const float* Trow = T + ((rel * 8 + h) * 16) * 16 + ec;
        float s = 0.f;
        if (i < 128) {
            const float* wrow = Wbase + i * 128 + h * 16;
#pragma unroll
            for (int d = 0; d < 16; d++) s += wrow[d] * Trow[d * 16];
        } else {
            const float* brow = bbase + h * 16;
#pragma unroll
            for (int d = 0; d < 16; d++) s += brow[d] * Trow[d * 16];
        }
        val = s;
    }

    float* Wc = t ? g_WcatB : g_WcatA;
    float* bc = t ? g_bcatB : g_bcatA;
    if (i < 128) Wc[i * 640 + c] = val;
    else         bc[c] = val;
}

// ---------------- bucket build: zero counters, then direct scatter ----------------
__global__ void zero_cnt_kernel()
{
    int i = blockIdx.x * blockDim.x + threadIdx.x;
    if (i < 4 * NNODE) ((int*)g_cnt)[i] = 0;
}

__global__ void scatter_kernel(GraphArgs ga)
{
    int r = blockIdx.y;
    int i = blockIdx.x * blockDim.x + threadIdx.x;
    if (i >= ga.E[r]) return;
    int d = ga.dst[r][i];
    int pos = atomicAdd(&g_cnt[r][d], 1);
    if (pos < CAP)
        g_srcS[r][(size_t)d * CAP + pos] = ga.src[r][i];
}

// ---------------- tf32 tensor-core GEMM: 128x128x32 block, 8 warps, 64x32/warp ----
// C[M,Ncols] = A[M,K] @ W[K,Ncols] + bias. blockIdx.z picks the (A,W,bias,C) set.
__global__ __launch_bounds__(256) void gemm_bias_tf32(
    const float* __restrict__ A0, const float* __restrict__ W0,
    const float* __restrict__ bias0, float* __restrict__ C0,
    const float* __restrict__ A1, const float* __restrict__ W1,
    const float* __restrict__ bias1, float* __restrict__ C1,
    int M, int Ncols, int K)
{
    const float* A    = blockIdx.z ? A1 : A0;
    const float* W    = blockIdx.z ? W1 : W0;
    const float* bias = blockIdx.z ? bias1 : bias0;
    float*       C    = blockIdx.z ? C1 : C0;

    __shared__ float As[128][36];    // 128 x 32 tile, stride 36 (conflict-free frags)
    __shared__ float Bs[32][136];    // 32 x 128 tile, stride 136 (8k+n banks)

    const int tid = threadIdx.x;
    const int lane = tid & 31;
    const int wid = tid >> 5;
    const int wm = wid & 1;          // warp row: 2 x 64
    const int wn = wid >> 1;         // warp col: 4 x 32
    const int rowBlock = blockIdx.y * 128;
    const int colBlock = blockIdx.x * 128;

    float acc[4][4][4];              // [mfrag][nfrag][reg]
#pragma unroll
    for (int f = 0; f < 4; f++)
#pragma unroll
        for (int n = 0; n < 4; n++)
#pragma unroll
            for (int r = 0; r < 4; r++) acc[f][n][r] = 0.f;

    const int ar = tid >> 1;                // A stage row 0..127
    const int ac = (tid & 1) << 4;          // 0 or 16
    const int br = tid >> 3;                // B stage row 0..31
    const int bc = (tid & 7) << 4;          // 0..112
    const int agrow = rowBlock + ar;

    for (int kk = 0; kk < K; kk += 32) {
        {   // stage A (convert to tf32 at store)
            float4 v[4];
            if (agrow < M) {
                const float* ap = A + (size_t)agrow * K + kk + ac;
#pragma unroll
                for (int j = 0; j < 4; j++) v[j] = ((const float4*)ap)[j];
            } else {
#pragma unroll
                for (int j = 0; j < 4; j++) v[j] = make_float4(0.f, 0.f, 0.f, 0.f);
            }
#pragma unroll
            for (int j = 0; j < 4; j++) {
                float4 t;
                t.x = __uint_as_float(f2tf(v[j].x));
                t.y = __uint_as_float(f2tf(v[j].y));
                t.z = __uint_as_float(f2tf(v[j].z));
                t.w = __uint_as_float(f2tf(v[j].w));
                *(float4*)&As[ar][ac + j * 4] = t;
            }
        }
        {   // stage B
            const float* wp = W + (size_t)(kk + br) * Ncols + colBlock + bc;
#pragma unroll
            for (int j = 0; j < 4; j++) {
                float4 v = ((const float4*)wp)[j];
                float4 t;
                t.x = __uint_as_float(f2tf(v.x));
                t.y = __uint_as_float(f2tf(v.y));
                t.z = __uint_as_float(f2tf(v.z));
                t.w = __uint_as_float(f2tf(v.w));
                *(float4*)&Bs[br][bc + j * 4] = t;
            }
        }
        __syncthreads();

#pragma unroll
        for (int k8 = 0; k8 < 32; k8 += 8) {
            unsigned a[4][4], b[4][2];
            const int ar0 = wm * 64 + (lane >> 2);
            const int acx = k8 + (lane & 3);
#pragma unroll
            for (int f = 0; f < 4; f++) {
                a[f][0] = __float_as_uint(As[ar0 + f * 16][acx]);
                a[f][1] = __float_as_uint(As[ar0 + f * 16 + 8][acx]);
                a[f][2] = __float_as_uint(As[ar0 + f * 16][acx + 4]);
                a[f][3] = __float_as_uint(As[ar0 + f * 16 + 8][acx + 4]);
            }
            const int brx = k8 + (lane & 3);
            const int bc0 = wn * 32 + (lane >> 2);
#pragma unroll
            for (int n = 0; n < 4; n++) {
                b[n][0] = __float_as_uint(Bs[brx][bc0 + n * 8]);
                b[n][1] = __float_as_uint(Bs[brx + 4][bc0 + n * 8]);
            }
#pragma unroll
            for (int f = 0; f < 4; f++)
#pragma unroll
                for (int n = 0; n < 4; n++)
                    mma_tf32(acc[f][n], a[f], b[n]);
        }
        __syncthreads();
    }

    // epilogue: fragment layout -> global, + bias
#pragma unroll
    for (int f = 0; f < 4; f++) {
        int r0 = rowBlock + wm * 64 + f * 16 + (lane >> 2);
#pragma unroll
        for (int n = 0; n < 4; n++) {
            int c0 = colBlock + wn * 32 + n * 8 + ((lane & 3) << 1);
            float2 bb = *(const float2*)&bias[c0];
            if (r0 < M) {
                float2 o;
                o.x = acc[f][n][0] + bb.x;
                o.y = acc[f][n][1] + bb.y;
                *(float2*)&C[(size_t)r0 * Ncols + c0] = o;
            }
            if (r0 + 8 < M) {
                float2 o;
                o.x = acc[f][n][2] + bb.x;
                o.y = acc[f][n][3] + bb.y;
                *(float2*)&C[(size_t)(r0 + 8) * Ncols + c0] = o;
            }
        }
    }
}

// ---------------- per-relation edge accumulation (register softmax, unroll 4) ------
__device__ __forceinline__ void edge_step(
    const float* __restrict__ Kb, const float* __restrict__ Vb, int s,
    float4 q, float prih, float4& acc, float& ss, int lane)
{
    float4 k = ((const float4*)(Kb + (size_t)s * PCOLS))[lane];
    float4 v = ((const float4*)(Vb + (size_t)s * PCOLS))[lane];
    float p = k.x * q.x + k.y * q.y + k.z * q.z + k.w * q.w;
    p += __shfl_xor_sync(0xffffffffu, p, 1);
    p += __shfl_xor_sync(0xffffffffu, p, 2);
    float e = __expf(p * prih);
    ss += e;
    acc.x += e * v.x; acc.y += e * v.y; acc.z += e * v.z; acc.w += e * v.w;
}

__device__ __forceinline__ void rel_accum(
    const float* __restrict__ Kb, const float* __restrict__ Vb,
    const int* __restrict__ bucket, int n,
    float4 q, float prih, int lane, float4& acc, float& ss)
{
    acc = make_float4(0.f, 0.f, 0.f, 0.f);
    ss = 0.f;
    int i = 0;
    for (; i + 4 <= n; i += 4) {
        int s0 = bucket[i], s1 = bucket[i + 1], s2 = bucket[i + 2], s3 = bucket[i + 3];
        float4 k0 = ((const float4*)(Kb + (size_t)s0 * PCOLS))[lane];
        float4 v0 = ((const float4*)(Vb + (size_t)s0 * PCOLS))[lane];
        float4 k1 = ((const float4*)(Kb + (size_t)s1 * PCOLS))[lane];
        float4 v1 = ((const float4*)(Vb + (size_t)s1 * PCOLS))[lane];
        float4 k2 = ((const float4*)(Kb + (size_t)s2 * PCOLS))[lane];
        float4 v2 = ((const float4*)(Vb + (size_t)s2 * PCOLS))[lane];
        float4 k3 = ((const float4*)(Kb + (size_t)s3 * PCOLS))[lane];
        float4 v3 = ((const float4*)(Vb + (size_t)s3 * PCOLS))[lane];
        float p0 = k0.x * q.x + k0.y * q.y + k0.z * q.z + k0.w * q.w;
        float p1 = k1.x * q.x + k1.y * q.y + k1.z * q.z + k1.w * q.w;
        float p2 = k2.x * q.x + k2.y * q.y + k2.z * q.z + k2.w * q.w;
        float p3 = k3.x * q.x + k3.y * q.y + k3.z * q.z + k3.w * q.w;
        p0 += __shfl_xor_sync(0xffffffffu, p0, 1);
        p1 += __shfl_xor_sync(0xffffffffu, p1, 1);
        p2 += __shfl_xor_sync(0xffffffffu, p2, 1);
        p3 += __shfl_xor_sync(0xffffffffu, p3, 1);
        p0 += __shfl_xor_sync(0xffffffffu, p0, 2);
        p1 += __shfl_xor_sync(0xffffffffu, p1, 2);
        p2 += __shfl_xor_sync(0xffffffffu, p2, 2);
        p3 += __shfl_xor_sync(0xffffffffu, p3, 2);
        float e0 = __expf(p0 * prih);
        float e1 = __expf(p1 * prih);
        float e2 = __expf(p2 * prih);
        float e3 = __expf(p3 * prih);
        ss += (e0 + e1) + (e2 + e3);
        acc.x += e0 * v0.x + e1 * v1.x + e2 * v2.x + e3 * v3.x;
        acc.y += e0 * v0.y + e1 * v1.y + e2 * v2.y + e3 * v3.y;
        acc.z += e0 * v0.z + e1 * v1.z + e2 * v2.z + e3 * v3.z;
        acc.w += e0 * v0.w + e1 * v1.w + e2 * v2.w + e3 * v3.w;
    }
    for (; i < n; i++)
        edge_step(Kb, Vb, bucket[i], q, prih, acc, ss, lane);
}

// ---------------- aggregate: one warp per (dst node, node type); both relations ----
__global__ __launch_bounds__(256) void agg_kernel(const float* __restrict__ pri)
{
    int t = blockIdx.y;                 // node type: 0=a, 1=b
    int wid = threadIdx.x >> 5;
    int lane = threadIdx.x & 31;
    int d = blockIdx.x * 8 + wid;
    if (d >= NNODE) return;
    int hh = lane >> 2;

    const float* Qb = (t ? g_Pb : g_Pa) + 512;
    int r0 = t ? 1 : 0;     // a-type src relation
    int r1 = t ? 3 : 2;     // b-type src relation
    const float* K0 = g_Pa + (t ? 128 : 0);
    const float* V0 = g_Pa + (t ? 384 : 256);
    const float* K1 = g_Pb + (t ? 128 : 0);
    const float* V1 = g_Pb + (t ? 384 : 256);

    float4 q = ((const float4*)(Qb + (size_t)d * PCOLS))[lane];
    float pri0 = __ldg(pri + r0 * 8 + hh) * 0.25f;
    float pri1 = __ldg(pri + r1 * 8 + hh) * 0.25f;

    int n0 = min(g_cnt[r0][d], CAP);
    int n1 = min(g_cnt[r1][d], CAP);

    float4 a0, a1;
    float s0, s1;
    rel_accum(K0, V0, &g_srcS[r0][(size_t)d * CAP], n0, q, pri0, lane, a0, s0);
    rel_accum(K1, V1, &g_srcS[r1][(size_t)d * CAP], n1, q, pri1, lane, a1, s1);

    float i0 = (s0 > 0.f) ? 0.5f / s0 : 0.f;
    float i1 = (s1 > 0.f) ? 0.5f / s1 : 0.f;
    float4 o;
    o.x = a0.x * i0 + a1.x * i1;
    o.y = a0.y * i0 + a1.y * i1;
    o.z = a0.z * i0 + a1.z * i1;
    o.w = a0.w * i0 + a1.w * i1;
    *(float4*)(&g_agg[t][(size_t)d * 128 + lane * 4]) = o;
}

// ---------------- final GEMM + skip epilogue (both node types, blockIdx.z) ----------
__global__ __launch_bounds__(256) void gemm_final_kernel(
    const float* __restrict__ Wa, const float* __restrict__ ba,
    const float* __restrict__ h_a, const float* __restrict__ h_b,
    const float* __restrict__ skipv, float* __restrict__ outbase, int M)
{
    const int K = 128, Ncols = 128;
    const int t = blockIdx.z;
    const float* Agg  = g_agg[t];
    const float* W    = Wa + t * 16384;
    const float* bias = ba + t * 128;
    const float* hres = t ? h_b : h_a;
    float* out = outbase + (size_t)t * M * 128;

    __shared__ float As[16][132];
    __shared__ float Bs[16][128];
    const int tid = threadIdx.x;
    const int tx = tid & 15;
    const int ty = tid >> 4;
    const int rowBlock = blockIdx.y * 128;

    float acc[8][8];
#pragma unroll
    for (int i = 0; i < 8; i++)
#pragma unroll
        for (int j = 0; j < 8; j++) acc[i][j] = 0.f;

    const int lr = tid >> 1;
    const int lkc = (tid & 1) << 3;
    const int bk = tid >> 4;
    const int bc = (tid & 15) << 3;
    const int grow = rowBlock + lr;

    for (int kk = 0; kk < K; kk += 16) {
        {
            float4 v0 = make_float4(0.f, 0.f, 0.f, 0.f), v1 = v0;
            if (grow < M) {
                const float* ap = Agg + (size_t)grow * K + kk + lkc;
                v0 = *(const float4*)ap;
                v1 = *(const float4*)(ap + 4);
            }
            As[lkc + 0][lr] = v0.x; As[lkc + 1][lr] = v0.y;
            As[lkc + 2][lr] = v0.z; As[lkc + 3][lr] = v0.w;
            As[lkc + 4][lr] = v1.x; As[lkc + 5][lr] = v1.y;
            As[lkc + 6][lr] = v1.z; As[lkc + 7][lr] = v1.w;
        }
        {
            const float* wp = W + (size_t)(kk + bk) * Ncols + bc;
            float4 v0 = *(const float4*)wp;
            float4 v1 = *(const float4*)(wp + 4);
            *(float4*)&Bs[bk][bc]     = v0;
            *(float4*)&Bs[bk][bc + 4] = v1;
        }
        __syncthreads();
#pragma unroll
        for (int k = 0; k < 16; k++) {
            float4 a0 = *(const float4*)&As[k][ty * 8];
            float4 a1 = *(const float4*)&As[k][ty * 8 + 4];
            float4 b0 = *(const float4*)&Bs[k][tx * 8];
            float4 b1 = *(const float4*)&Bs[k][tx * 8 + 4];
            float a[8] = {a0.x, a0.y, a0.z, a0.w, a1.x, a1.y, a1.z, a1.w};
            float b[8] = {b0.x, b0.y, b0.z, b0.w, b1.x, b1.y, b1.z, b1.w};
#pragma unroll
            for (int i = 0; i < 8; i++)
#pragma unroll
                for (int j = 0; j < 8; j++) acc[i][j] += a[i] * b[j];
        }
        __syncthreads();
    }

    float al = 1.f / (1.f + expf(-skipv[t]));
    float om = 1.f - al;
#pragma unroll
    for (int i = 0; i < 8; i++) {
        int row = rowBlock + ty * 8 + i;
        if (row < M) {
            float* op = out + (size_t)row * Ncols + tx * 8;
            const float* hp = hres + (size_t)row * Ncols + tx * 8;
            float4 h0 = *(const float4*)hp;
            float4 h1 = *(const float4*)(hp + 4);
            float4 o0, o1;
            o0.x = al * (acc[i][0] + bias[tx * 8 + 0]) + om * h0.x;
            o0.y = al * (acc[i][1] + bias[tx * 8 + 1]) + om * h0.y;
            o0.z = al * (acc[i][2] + bias[tx * 8 + 2]) + om * h0.z;
            o0.w = al * (acc[i][3] + bias[tx * 8 + 3]) + om * h0.w;
            o1.x = al * (acc[i][4] + bias[tx * 8 + 4]) + om * h1.x;
            o1.y = al * (acc[i][5] + bias[tx * 8 + 5]) + om * h1.y;
            o1.z = al * (acc[i][6] + bias[tx * 8 + 6]) + om * h1.z;
            o1.w = al * (acc[i][7] + bias[tx * 8 + 7]) + om * h1.w;
            *(float4*)op = o0;
            *(float4*)(op + 4) = o1;
        }
    }
}

// ---------------- launch ----------------
extern "C" void kernel_launch(void* const* d_in, const int* in_sizes, int n_in,
                              void* d_out, int out_size)
{
    const float* h_a  = (const float*)d_in[0];
    const float* h_b  = (const float*)d_in[1];
    const float* Wk   = (const float*)d_in[2];
    const float* bk   = (const float*)d_in[3];
    const float* Wq   = (const float*)d_in[4];
    const float* bq   = (const float*)d_in[5];
    const float* Wv   = (const float*)d_in[6];
    const float* bv   = (const float*)d_in[7];
    const float* Wa   = (const float*)d_in[8];
    const float* ba   = (const float*)d_in[9];
    const float* att  = (const float*)d_in[10];
    const float* msg  = (const float*)d_in[11];
    const float* pri  = (const float*)d_in[12];
    const float* skip = (const float*)d_in[13];

    GraphArgs ga;
    int Emax = 0;
    for (int r = 0; r < 4; r++) {
        ga.src[r] = (const int*)d_in[14 + 2 * r];
        ga.dst[r] = (const int*)d_in[15 + 2 * r];
        ga.E[r] = in_sizes[14 + 2 * r];
        if (ga.E[r] > Emax) Emax = ga.E[r];
    }

    float *Pa, *Pb, *WcA, *WcB, *bcA, *bcB;
    cudaGetSymbolAddress((void**)&Pa,  g_Pa);
    cudaGetSymbolAddress((void**)&Pb,  g_Pb);
    cudaGetSymbolAddress((void**)&WcA, g_WcatA);
    cudaGetSymbolAddress((void**)&WcB, g_WcatB);
    cudaGetSymbolAddress((void**)&bcA, g_bcatA);
    cudaGetSymbolAddress((void**)&bcB, g_bcatB);

    // bucket build: zero counters, then direct padded scatter (no hist/scan)
    zero_cnt_kernel<<<(4 * NNODE + 255) / 256, 256>>>();
    prep_kernel<<<dim3((129 * 640 + 255) / 256, 2), 256>>>(Wk, bk, Wq, bq, Wv, bv, att, msg);
    scatter_kernel<<<dim3((Emax + 255) / 256, 4), 256>>>(ga);

    // projections: tf32 tensor-core GEMM (both node types, one launch)
    gemm_bias_tf32<<<dim3(PCOLS / 128, (NNODE + 127) / 128, 2), 256>>>(
        h_a, WcA, bcA, Pa, h_b, WcB, bcB, Pb, NNODE, PCOLS, 128);

    // per-node attention aggregation (no atomics, unroll-4 MLP)
    agg_kernel<<<dim3((NNODE + 7) / 8, 2), 256>>>(pri);

    // both final GEMMs in one launch (blockIdx.z)
    gemm_final_kernel<<<dim3(1, (NNODE + 127) / 128, 2), 256>>>(
        Wa, ba, h_a, h_b, skip, (float*)d_out, NNODE);
}